// round 15
// baseline (speedup 1.0000x reference)
#include <cuda_runtime.h>
#include <cuda_bf16.h>
#include <stdint.h>
#include <math.h>

// ---------------------------------------------------------------- dims
static constexpr int Bb = 64;
static constexpr int Ss = 512;
static constexpr int Ee = 512;
static constexpr int Hh = 8;
static constexpr int Dd = 64;
static constexpr int Mm = Bb * Ss;     // 32768
static constexpr int HD = Hh * Dd;     // 512

// ---------------------------------------------------------------- scratch
__device__ __nv_bfloat16 g_Ah[Mm * Ee];
__device__ __nv_bfloat16 g_Al[Mm * Ee];
__device__ __nv_bfloat16 g_ATh[Mm * HD];
__device__ __nv_bfloat16 g_ATl[Mm * HD];
__device__ __nv_bfloat16 g_Bh[2048 * 512];
__device__ __nv_bfloat16 g_Bl[2048 * 512];
__device__ __nv_bfloat16 g_Qh[Mm * HD];
__device__ __nv_bfloat16 g_Ql[Mm * HD];
// K/V stored GLOBALLY COMPACTED: batch b keys at rows [off[b], off[b]+nk[b])
// (+256 pad rows: last-batch tile overrun always lands on written data)
__device__ __nv_bfloat16 g_Kh[(Mm + 256) * HD];
__device__ __nv_bfloat16 g_Kl[(Mm + 256) * HD];
__device__ __nv_bfloat16 g_Vh[(Mm + 256) * HD];
__device__ __nv_bfloat16 g_Vl[(Mm + 256) * HD];
// mask compaction
__device__ int g_idx[Bb * Ss];
__device__ int g_nt[Bb];
__device__ int g_nk[Bb];

// ---------------------------------------------------------------- helpers
__device__ __forceinline__ void pack_hilo(float v0, float v1, uint32_t& hp, uint32_t& lp) {
    asm("cvt.rn.bf16x2.f32 %0, %1, %2;" : "=r"(hp) : "f"(v1), "f"(v0));
    float h0 = __uint_as_float(hp << 16);
    float h1 = __uint_as_float(hp & 0xFFFF0000u);
    float r0 = v0 - h0;
    float r1 = v1 - h1;
    asm("cvt.rn.bf16x2.f32 %0, %1, %2;" : "=r"(lp) : "f"(r1), "f"(r0));
}
__device__ __forceinline__ float ex2(float x) {
    float r;
    asm("ex2.approx.f32 %0, %1;" : "=f"(r) : "f"(x));
    return r;
}
__device__ __forceinline__ uint32_t smem_u32(const void* p) {
    uint32_t a;
    asm("{ .reg .u64 t; cvta.to.shared.u64 t, %1; cvt.u32.u64 %0, t; }" : "=r"(a) : "l"(p));
    return a;
}
__device__ __forceinline__ void ldsm4(uint32_t r[4], uint32_t addr) {
    asm volatile("ldmatrix.sync.aligned.m8n8.x4.shared.b16 {%0,%1,%2,%3}, [%4];"
                 : "=r"(r[0]), "=r"(r[1]), "=r"(r[2]), "=r"(r[3]) : "r"(addr));
}
__device__ __forceinline__ void ldsm4t(uint32_t r[4], uint32_t addr) {
    asm volatile("ldmatrix.sync.aligned.m8n8.x4.trans.shared.b16 {%0,%1,%2,%3}, [%4];"
                 : "=r"(r[0]), "=r"(r[1]), "=r"(r[2]), "=r"(r[3]) : "r"(addr));
}
__device__ __forceinline__ void mma16816(float d[4], const uint32_t a[4],
                                         uint32_t b0, uint32_t b1) {
    asm volatile("mma.sync.aligned.m16n8k16.row.col.f32.bf16.bf16.f32 "
                 "{%0,%1,%2,%3}, {%4,%5,%6,%7}, {%8,%9}, {%0,%1,%2,%3};"
                 : "+f"(d[0]), "+f"(d[1]), "+f"(d[2]), "+f"(d[3])
                 : "r"(a[0]), "r"(a[1]), "r"(a[2]), "r"(a[3]), "r"(b0), "r"(b1));
}
__device__ __forceinline__ void cpasync16(uint32_t saddr, const void* g) {
    asm volatile("cp.async.cg.shared.global [%0], [%1], 16;" :: "r"(saddr), "l"(g));
}
__device__ __forceinline__ void cpcommit() {
    asm volatile("cp.async.commit_group;" ::: "memory");
}
template <int N>
__device__ __forceinline__ void cpwait() {
    asm volatile("cp.async.wait_group %0;" :: "n"(N) : "memory");
}

// ---------------------------------------------------------------- mask compaction
__global__ __launch_bounds__(512) void mask_compact_kernel(const float* __restrict__ mask) {
    const int b = blockIdx.x, t = threadIdx.x;
    const int wid = t >> 5, lane = t & 31;
    const bool keep = (mask[(size_t)b * 512 + t] == 0.0f);
    const unsigned bal = __ballot_sync(0xffffffffu, keep);
    __shared__ int wcnt[16], woff[16], snk;
    if (lane == 0) wcnt[wid] = __popc(bal);
    __syncthreads();
    if (t == 0) {
        int s = 0;
        for (int i = 0; i < 16; i++) { woff[i] = s; s += wcnt[i]; }
        snk = s;
        g_nk[b] = s;
        g_nt[b] = (s + 63) >> 6;
    }
    __syncthreads();
    const int nk = snk;
    const int pos = woff[wid] + __popc(bal & ((1u << lane) - 1));
    if (keep) g_idx[b * 512 + pos] = t;
    if (t >= nk) g_idx[b * 512 + t] = 0;
}

// ---------------------------------------------------------------- fused prep
__global__ __launch_bounds__(256) void prep_kernel(const float* __restrict__ x,
                                                   const float* __restrict__ be,
                                                   const float* __restrict__ WQ,
                                                   const float* __restrict__ WK,
                                                   const float* __restrict__ WV,
                                                   const float* __restrict__ WO) {
    if (blockIdx.x < 16384) {
        uint32_t i4 = blockIdx.x * 256 + threadIdx.x;
        int m = i4 >> 7;
        int k = (i4 & 127) << 2;
        const float4 xv = *(const float4*)&x[(size_t)m * Ee + k];
        const float4 bv = *(const float4*)&be[(size_t)(m & (Ss - 1)) * Ee + k];
        uint32_t h01, h23, l01, l23;
        pack_hilo(xv.x + bv.x, xv.y + bv.y, h01, l01);
        pack_hilo(xv.z + bv.z, xv.w + bv.w, h23, l23);
        size_t o = (size_t)m * Ee + k;
        *(uint32_t*)&g_Ah[o]     = h01;
        *(uint32_t*)&g_Ah[o + 2] = h23;
        *(uint32_t*)&g_Al[o]     = l01;
        *(uint32_t*)&g_Al[o + 2] = l23;
    } else {
        uint32_t idx = (blockIdx.x - 16384) * 256 + threadIdx.x;
        int r = idx >> 9;
        int k = idx & 511;
        float v;
        if (r < 1536) {
            int z = r >> 9;
            int n = r & 511;
            const float* W = (z == 0) ? WQ : (z == 1) ? WK : WV;
            v = W[(size_t)(n >> 6) * (Ee * Dd) + (size_t)k * Dd + (n & 63)];
        } else {
            int n = r - 1536;
            v = WO[(size_t)k * Ee + n];
        }
        uint32_t hp, lp;
        pack_hilo(v, v, hp, lp);
        g_Bh[idx] = *(__nv_bfloat16*)&hp;
        g_Bl[idx] = *(__nv_bfloat16*)&lp;
    }
}

// ---------------------------------------------------------------- HMMA GEMM
// 128x128 CTA, 4 warps, warp tile 64x64, cp.async 3-stage.
static constexpr int SA_H = 0;
static constexpr int SA_L = 8192;
static constexpr int SB_H = 16384;
static constexpr int SB_L = 24576;
static constexpr int GSTAGE = 32768;
static constexpr int GEMM_SMEM = 3 * GSTAGE;   // 96 KB

static constexpr float SCALE2 = 0.044194173824159216f * 1.4426950408889634f; // 1/sqrt(E)*log2(e)

template <int WHICH>
__global__ __launch_bounds__(128, 2) void gemm_bf16x3_kernel(float* __restrict__ Cout)
{
    extern __shared__ __align__(16) char sm[];
    const uint32_t sb = smem_u32(sm);
    const int tid  = threadIdx.x;
    const int wid  = tid >> 5;
    const int lane = tid & 31;

    const int mt = blockIdx.x;
    const int m0 = mt * 128;
    const int n0 = blockIdx.y * 128;
    const int z  = (WHICH == 0) ? blockIdx.z : 0;

    __shared__ int s_off[65];
    if (WHICH == 0 && z > 0) {
        // per-CTA prefix scan of batch key counts (L2-cached reads, ~64 each)
        if (tid < 64) {
            int s = 0;
            for (int i = 0; i < tid; i++) s += g_nk[i];
            s_off[tid] = s;
            if (tid == 63) s_off[64] = s + g_nk[63];
        }
        __syncthreads();
        const int ntot_tiles = (s_off[64] + 64 + 127) >> 7;  // +64: cover attn tile overrun
        if (mt >= ntot_tiles) return;
    } else if (WHICH == 0) {
        if (mt >= 256) return;   // Q uses exactly 256 m-tiles
    }

    const __nv_bfloat16* Ah = (WHICH == 0) ? g_Ah : g_ATh;
    const __nv_bfloat16* Al = (WHICH == 0) ? g_Al : g_ATl;
    const size_t boff = (WHICH == 0) ? (size_t)z * 512 * 512 : (size_t)1536 * 512;
    const __nv_bfloat16* Bh = g_Bh + boff;
    const __nv_bfloat16* Bl = g_Bl + boff;

    const int m_warp = (wid & 1) * 64;
    const int n_warp = (wid >> 1) * 64;

    const int rA   = (lane & 7) + ((lane >> 3) & 1) * 8;
    const int kbA  = lane >> 4;
    const int sxA  = (rA >> 1) & 3;
    const int rB   = (lane & 7) + (lane >> 4) * 8;
    const int kbB  = (lane >> 3) & 1;
    const int sxB  = (rB >> 1) & 3;

    float acc[4][8][4];
#pragma unroll
    for (int i = 0; i < 4; i++)
#pragma unroll
        for (int j = 0; j < 8; j++)
#pragma unroll
            for (int u = 0; u < 4; u++) acc[i][j][u] = 0.f;

    int grow[4], gc8[4];
    uint32_t so[4];
    size_t aoff[4], bo[4];
#pragma unroll
    for (int i = 0; i < 4; i++) {
        int f = tid + i * 128;
        grow[i] = f >> 2;
        gc8[i]  = f & 3;
        so[i]   = grow[i] * 64 + ((gc8[i] ^ ((grow[i] >> 1) & 3)) * 16);
        int arow = m0 + grow[i];
        if (WHICH == 0 && z > 0) {
            const int r = m0 + grow[i];          // global compacted row
            int bsel = 0;
            while (bsel < 63 && s_off[bsel + 1] <= r) ++bsel;
            int lp = r - s_off[bsel];
            if (lp > 511) lp = 511;
            arow = bsel * 512 + g_idx[bsel * 512 + lp];
        }
        aoff[i] = (size_t)arow * 512 + gc8[i] * 8;
        bo[i]   = (size_t)(n0 + grow[i]) * 512 + gc8[i] * 8;
    }

    auto load_chunk = [&](int k0, int stage) {
        uint32_t s_ = sb + stage * GSTAGE;
#pragma unroll
        for (int i = 0; i < 4; i++) {
            cpasync16(s_ + SA_H + so[i], Ah + aoff[i] + k0);
            cpasync16(s_ + SA_L + so[i], Al + aoff[i] + k0);
            cpasync16(s_ + SB_H + so[i], Bh + bo[i] + k0);
            cpasync16(s_ + SB_L + so[i], Bl + bo[i] + k0);
        }
        cpcommit();
    };

    load_chunk(0, 0);
    load_chunk(32, 1);

    for (int c = 0; c < 16; ++c) {
        if (c < 15) cpwait<1>(); else cpwait<0>();
        __syncthreads();
        if (c + 2 < 16) load_chunk((c + 2) * 32, (c + 2) % 3);

        const uint32_t sbs = sb + (c % 3) * GSTAGE;
#pragma unroll
        for (int kk = 0; kk < 2; ++kk) {
            uint32_t ah[4][4], al[4][4];
#pragma unroll
            for (int tm = 0; tm < 4; ++tm) {
                uint32_t ro = (uint32_t)(m_warp + tm * 16 + rA) * 64 +
                              (uint32_t)(((kk * 2 + kbA) ^ sxA) * 16);
                ldsm4(ah[tm], sbs + SA_H + ro);
                ldsm4(al[tm], sbs + SA_L + ro);
            }
#pragma unroll
            for (int tp = 0; tp < 4; ++tp) {
                uint32_t bh[4], bl[4];
                uint32_t ro = (uint32_t)(n_warp + tp * 16 + rB) * 64 +
                              (uint32_t)(((kk * 2 + kbB) ^ sxB) * 16);
                ldsm4(bh, sbs + SB_H + ro);
                ldsm4(bl, sbs + SB_L + ro);
#pragma unroll
                for (int tm = 0; tm < 4; ++tm) {
                    mma16816(acc[tm][2 * tp],     ah[tm], bh[0], bh[1]);
                    mma16816(acc[tm][2 * tp],     ah[tm], bl[0], bl[1]);
                    mma16816(acc[tm][2 * tp],     al[tm], bh[0], bh[1]);
                    mma16816(acc[tm][2 * tp + 1], ah[tm], bh[2], bh[3]);
                    mma16816(acc[tm][2 * tp + 1], ah[tm], bl[2], bl[3]);
                    mma16816(acc[tm][2 * tp + 1], al[tm], bh[2], bh[3]);
                }
            }
        }
    }

    // epilogue
    if (WHICH == 0) {
        if (z == 0) {
#pragma unroll
            for (int i = 0; i < 4; i++)
#pragma unroll
                for (int j = 0; j < 8; j++)
#pragma unroll
                    for (int u = 0; u < 4; u++) acc[i][j][u] *= SCALE2;
        }
        __nv_bfloat16* Ch = (z == 0) ? g_Qh : (z == 1) ? g_Kh : g_Vh;
        __nv_bfloat16* Cl = (z == 0) ? g_Ql : (z == 1) ? g_Kl : g_Vl;
#pragma unroll
        for (int tm = 0; tm < 4; ++tm) {
            const int m = m0 + m_warp + tm * 16 + (lane >> 2);
#pragma unroll
            for (int tn = 0; tn < 8; ++tn) {
                const int n = n0 + n_warp + tn * 8 + (lane & 3) * 2;
                size_t o0 = (size_t)m * 512 + n;
                size_t o1 = (size_t)(m + 8) * 512 + n;
                uint32_t hp0, lp0, hp1, lp1;
                pack_hilo(acc[tm][tn][0], acc[tm][tn][1], hp0, lp0);
                pack_hilo(acc[tm][tn][2], acc[tm][tn][3], hp1, lp1);
                *(uint32_t*)&Ch[o0] = hp0;
                *(uint32_t*)&Cl[o0] = lp0;
                *(uint32_t*)&Ch[o1] = hp1;
                *(uint32_t*)&Cl[o1] = lp1;
            }
        }
    } else {
#pragma unroll
        for (int tm = 0; tm < 4; ++tm) {
            const int m = m0 + m_warp + tm * 16 + (lane >> 2);
#pragma unroll
            for (int tn = 0; tn < 8; ++tn) {
                const int n = n0 + n_warp + tn * 8 + (lane & 3) * 2;
                *(float2*)&Cout[(size_t)m * 512 + n] =
                    make_float2(acc[tm][tn][0], acc[tm][tn][1]);
                *(float2*)&Cout[(size_t)(m + 8) * 512 + n] =
                    make_float2(acc[tm][tn][2], acc[tm][tn][3]);
            }
        }
    }
}

// ---------------------------------------------------------------- tensor-core attention
// FA2-style, K/V globally compacted at base off[b]. Full tiles predicate-free;
// tail tile only ceil(rem/16) chunks (bit-identical: skipped chunks added 0).
static constexpr int A_QH = 0;
static constexpr int A_QL = 16384;
static constexpr int A_K0 = 32768;
static constexpr int A_V0 = 65536;
static constexpr int ATTN_SMEM = 98304;

__global__ __launch_bounds__(256, 2) void attn_mma_kernel()
{
    extern __shared__ char sm[];
    const uint32_t sb = smem_u32(sm);
    const int tid  = threadIdx.x;
    const int wid  = tid >> 5;
    const int lane = tid & 31;

    const int qt = blockIdx.x;
    const int h  = blockIdx.y;
    const int b  = blockIdx.z;
    const int mq = wid * 16;
    const size_t qrow0 = (size_t)b * 512 + qt * 128;

    __shared__ int s_koff;
    if (tid == 0) {
        int s = 0;
        for (int i = 0; i < b; i++) s += g_nk[i];
        s_koff = s;
    }
    const int nt = g_nt[b];
    const int nk = g_nk[b];
    const int kgmax = ((nk - (nt - 1) * 64) + 15) >> 4;
    __syncthreads();
    const int koff = s_koff;

#pragma unroll
    for (int i = 0; i < 4; i++) {
        int idx = tid + i * 256;
        int row = idx >> 3, c = idx & 7;
        uint32_t so = row * 128 + ((c ^ (row & 7)) * 16);
        size_t g = (qrow0 + row) * 512 + h * 64 + c * 8;
        cpasync16(sb + A_QH + so, &g_Qh[g]);
        cpasync16(sb + A_QL + so, &g_Ql[g]);
    }
#pragma unroll
    for (int i = 0; i < 2; i++) {
        int idx = tid + i * 256;
        int row = idx >> 3, c = idx & 7;
        uint32_t so = row * 128 + ((c ^ (row & 7)) * 16);
        size_t g = (size_t)(koff + row) * 512 + h * 64 + c * 8;
        cpasync16(sb + A_K0 + so, &g_Kh[g]);
        cpasync16(sb + A_K0 + 8192 + so, &g_Kl[g]);
        cpasync16(sb + A_V0 + so, &g_Vh[g]);
        cpasync16(sb + A_V0 + 8192 + so, &g_Vl[g]);
    }
    cpcommit();

    float accO[4][2][4];
#pragma unroll
    for (int i = 0; i < 4; i++)
#pragma unroll
        for (int j = 0; j < 2; j++)
#pragma unroll
            for (int u = 0; u < 4; u++) accO[i][j][u] = 0.f;
    float rs0 = 0.f, rs1 = 0.f;

    const int rowQ = mq + (lane & 7) + ((lane >> 3) & 1) * 8;
    const int cQ   = lane >> 4;
    const int rowK = (lane & 7) + (lane >> 4) * 8;
    const int cK   = (lane >> 3) & 1;
    const int rowV = (lane & 7) + ((lane >> 3) & 1) * 8;
    const int cV   = lane >> 4;

    // ---------------- full tiles (all keys valid: no predicates)
    for (int tile = 0; tile + 1 < nt; ++tile) {
        cpwait<0>();
        __syncthreads();

        {
            const int t1 = (tile + 1) * 64;
            const uint32_t kb1 = sb + A_K0 + ((tile + 1) & 1) * 16384;
            const uint32_t vb1 = sb + A_V0 + ((tile + 1) & 1) * 16384;
#pragma unroll
            for (int i = 0; i < 2; i++) {
                int idx = tid + i * 256;
                int row = idx >> 3, c = idx & 7;
                uint32_t so = row * 128 + ((c ^ (row & 7)) * 16);
                size_t g = (size_t)(koff + t1 + row) * 512 + h * 64 + c * 8;
                cpasync16(kb1 + so, &g_Kh[g]);
                cpasync16(kb1 + 8192 + so, &g_Kl[g]);
                cpasync16(vb1 + so, &g_Vh[g]);
                cpasync16(vb1 + 8192 + so, &g_Vl[g]);
            }
            cpcommit();
        }

        const uint32_t kb = sb + A_K0 + (tile & 1) * 16384;
        const uint32_t vb = sb + A_V0 + (tile & 1) * 16384;

        float accS[4][2][4];
#pragma unroll
        for (int i = 0; i < 4; i++)
#pragma unroll
            for (int j = 0; j < 2; j++)
#pragma unroll
                for (int u = 0; u < 4; u++) accS[i][j][u] = 0.f;

#pragma unroll
        for (int ks = 0; ks < 4; ++ks) {
            uint32_t qh[4], ql[4];
            {
                uint32_t so = rowQ * 128 + (((ks * 2 + cQ) ^ (rowQ & 7)) * 16);
                ldsm4(qh, sb + A_QH + so);
                ldsm4(ql, sb + A_QL + so);
            }
#pragma unroll
            for (int kg = 0; kg < 4; ++kg) {
                uint32_t kh[4], kl[4];
                int row = kg * 16 + rowK;
                uint32_t so = row * 128 + (((ks * 2 + cK) ^ (row & 7)) * 16);
                ldsm4(kh, kb + so);
                ldsm4(kl, kb + 8192 + so);
                mma16816(accS[kg][0], qh, kh[0], kh[1]);
                mma16816(accS[kg][1], qh, kh[2], kh[3]);
                mma16816(accS[kg][0], qh, kl[0], kl[1]);
                mma16816(accS[kg][1], qh, kl[2], kl[3]);
                mma16816(accS[kg][0], ql, kh[0], kh[1]);
                mma16816(accS[kg][1], ql, kh[2], kh[3]);
            }
        }

#pragma unroll
        for (int kc = 0; kc < 4; ++kc) {
            float p[2][4];
#pragma unroll
            for (int t8 = 0; t8 < 2; ++t8) {
                p[t8][0] = ex2(accS[kc][t8][0]);
                p[t8][1] = ex2(accS[kc][t8][1]);
                p[t8][2] = ex2(accS[kc][t8][2]);
                p[t8][3] = ex2(accS[kc][t8][3]);
                rs0 += p[t8][0] + p[t8][1];
                rs1 += p[t8][2] + p[t8][3];
            }
            uint32_t ph[4], pl[4];
            pack_hilo(p[0][0], p[0][1], ph[0], pl[0]);
            pack_hilo(p[0][2], p[0][3], ph[1], pl[1]);
            pack_hilo(p[1][0], p[1][1], ph[2], pl[2]);
            pack_hilo(p[1][2], p[1][3], ph[3], pl[3]);
#pragma unroll
            for (int dg = 0; dg < 4; ++dg) {
                uint32_t vh[4], vl[4];
                int row = kc * 16 + rowV;
                uint32_t so = row * 128 + (((dg * 2 + cV) ^ (row & 7)) * 16);
                ldsm4t(vh, vb + so);
                ldsm4t(vl, vb + 8192 + so);
                mma16816(accO[dg][0], ph, vh[0], vh[1]);
                mma16816(accO[dg][1], ph, vh[2], vh[3]);
                mma16816(accO[dg][0], ph, vl[0], vl[1]);
                mma16816(accO[dg][1], ph, vl[2], vl[3]);
                mma16816(accO[dg][0], pl, vh[0], vh[1]);
                mma16816(accO[dg][1], pl, vh[2], vh[3]);
            }
        }
    }

    // ---------------- tail tile (only kgmax chunks; predicated exp)
    {
        const int tile = nt - 1;
        cpwait<0>();
        __syncthreads();

        const uint32_t kb = sb + A_K0 + (tile & 1) * 16384;
        const uint32_t vb = sb + A_V0 + (tile & 1) * 16384;

        float accS[4][2][4];
#pragma unroll
        for (int i = 0; i < 4; i++)
#pragma unroll
            for (int j = 0; j < 2; j++)
#pragma unroll
                for (int u = 0; u < 4; u++) accS[i][j][u] = 0.f;

#pragma unroll
        for (int ks = 0; ks < 4; ++ks) {
            uint32_t qh[4], ql[4];
            {
                uint32_t so = rowQ * 128 + (((ks * 2 + cQ) ^ (rowQ & 7)) * 16);
                ldsm4(qh, sb + A_QH + so);
                ldsm4(ql, sb + A_QL + so);
            }
#pragma unroll
            for (int kg = 0; kg < 4; ++kg) {
                if (kg < kgmax) {
                    uint32_t kh[4], kl[4];
                    int row = kg * 16 + rowK;
                    uint32_t so = row * 128 + (((ks * 2 + cK) ^ (row & 7)) * 16);
                    ldsm4(kh, kb + so);
                    ldsm4(kl, kb + 8192 + so);
                    mma16816(accS[kg][0], qh, kh[0], kh[1]);
                    mma16816(accS[kg][1], qh, kh[2], kh[3]);
                    mma16816(accS[kg][0], qh, kl[0], kl[1]);
                    mma16816(accS[kg][1], qh, kl[2], kl[3]);
                    mma16816(accS[kg][0], ql, kh[0], kh[1]);
                    mma16816(accS[kg][1], ql, kh[2], kh[3]);
                }
            }
        }

        const int t0 = tile * 64;
#pragma unroll
        for (int kc = 0; kc < 4; ++kc) {
            if (kc < kgmax) {
                float p[2][4];
#pragma unroll
                for (int t8 = 0; t8 < 2; ++t8) {
                    int key = t0 + kc * 16 + t8 * 8 + (lane & 3) * 2;
                    bool v0 = key < nk;
                    bool v1 = key + 1 < nk;
                    p[t8][0] = v0 ? ex2(accS[kc][t8][0]) : 0.f;
                    p[t8][1] = v1 ? ex2(accS[kc][t8][1]) : 0.f;
                    p[t8][2] = v0 ? ex2(accS[kc][t8][2]) : 0.f;
                    p[t8][3] = v1 ? ex2(accS[kc][t8][3]) : 0.f;
                    rs0 += p[t8][0] + p[t8][1];
                    rs1 += p[t8][2] + p[t8][3];
                }
                uint32_t ph[4], pl[4];
                pack_hilo(p[0][0], p[0][1], ph[0], pl[0]);
                pack_hilo(p[0][2], p[0][3], ph[1], pl[1]);
                pack_hilo(p[1][0], p[1][1], ph[2], pl[2]);
                pack_hilo(p[1][2], p[1][3], ph[3], pl[3]);
#pragma unroll
                for (int dg = 0; dg < 4; ++dg) {
                    uint32_t vh[4], vl[4];
                    int row = kc * 16 + rowV;
                    uint32_t so = row * 128 + (((dg * 2 + cV) ^ (row & 7)) * 16);
                    ldsm4t(vh, vb + so);
                    ldsm4t(vl, vb + 8192 + so);
                    mma16816(accO[dg][0], ph, vh[0], vh[1]);
                    mma16816(accO[dg][1], ph, vh[2], vh[3]);
                    mma16816(accO[dg][0], ph, vl[0], vl[1]);
                    mma16816(accO[dg][1], ph, vl[2], vl[3]);
                    mma16816(accO[dg][0], pl, vh[0], vh[1]);
                    mma16816(accO[dg][1], pl, vh[2], vh[3]);
                }
            }
        }
    }

    rs0 += __shfl_xor_sync(0xffffffffu, rs0, 1);
    rs0 += __shfl_xor_sync(0xffffffffu, rs0, 2);
    rs1 += __shfl_xor_sync(0xffffffffu, rs1, 1);
    rs1 += __shfl_xor_sync(0xffffffffu, rs1, 2);
    const float inv0 = 1.f / rs0;
    const float inv1 = 1.f / rs1;

    const int r0 = mq + (lane >> 2);
    const int r1 = r0 + 8;
    const size_t g0 = (qrow0 + r0) * 512 + h * 64;
    const size_t g1 = (qrow0 + r1) * 512 + h * 64;
#pragma unroll
    for (int dg = 0; dg < 4; ++dg) {
#pragma unroll
        for (int t8 = 0; t8 < 2; ++t8) {
            int d = dg * 16 + t8 * 8 + (lane & 3) * 2;
            uint32_t hp0, lp0, hp1, lp1;
            pack_hilo(accO[dg][t8][0] * inv0, accO[dg][t8][1] * inv0, hp0, lp0);
            pack_hilo(accO[dg][t8][2] * inv1, accO[dg][t8][3] * inv1, hp1, lp1);
            *(uint32_t*)&g_ATh[g0 + d] = hp0;
            *(uint32_t*)&g_ATl[g0 + d] = lp0;
            *(uint32_t*)&g_ATh[g1 + d] = hp1;
            *(uint32_t*)&g_ATl[g1 + d] = lp1;
        }
    }
}

// ---------------------------------------------------------------- launch
extern "C" void kernel_launch(void* const* d_in, const int* in_sizes, int n_in,
                              void* d_out, int out_size)
{
    const float* x    = (const float*)d_in[0];
    const float* mask = (const float*)d_in[1];
    const float* WQ   = (const float*)d_in[2];
    const float* WK   = (const float*)d_in[3];
    const float* WV   = (const float*)d_in[4];
    const float* BE   = (const float*)d_in[5];
    const float* WO   = (const float*)d_in[6];
    float* out        = (float*)d_out;

    cudaFuncSetAttribute(attn_mma_kernel,
                         cudaFuncAttributeMaxDynamicSharedMemorySize, ATTN_SMEM);
    cudaFuncSetAttribute(gemm_bf16x3_kernel<0>,
                         cudaFuncAttributeMaxDynamicSharedMemorySize, GEMM_SMEM);
    cudaFuncSetAttribute(gemm_bf16x3_kernel<1>,
                         cudaFuncAttributeMaxDynamicSharedMemorySize, GEMM_SMEM);

    mask_compact_kernel<<<Bb, 512>>>(mask);
    prep_kernel<<<16384 + 4096, 256>>>(x, BE, WQ, WK, WV, WO);

    dim3 gq(258, 512 / 128, 3);   // mt up to 258 (K/V overrun tile); Q exits at 256
    gemm_bf16x3_kernel<0><<<gq, 128, GEMM_SMEM>>>(nullptr);

    dim3 ga(Ss / 128, Hh, Bb);
    attn_mma_kernel<<<ga, 256, ATTN_SMEM>>>();

    dim3 go(Mm / 128, 512 / 128);
    gemm_bf16x3_kernel<1><<<go, 128, GEMM_SMEM>>>(out);
}

// round 16
// speedup vs baseline: 1.1746x; 1.1746x over previous
#include <cuda_runtime.h>
#include <cuda_bf16.h>
#include <stdint.h>
#include <math.h>

// ---------------------------------------------------------------- dims
static constexpr int Bb = 64;
static constexpr int Ss = 512;
static constexpr int Ee = 512;
static constexpr int Hh = 8;
static constexpr int Dd = 64;
static constexpr int Mm = Bb * Ss;     // 32768
static constexpr int HD = Hh * Dd;     // 512

// ---------------------------------------------------------------- scratch
__device__ __nv_bfloat16 g_Ah[Mm * Ee];
__device__ __nv_bfloat16 g_Al[Mm * Ee];
__device__ __nv_bfloat16 g_ATh[Mm * HD];
__device__ __nv_bfloat16 g_ATl[Mm * HD];
__device__ __nv_bfloat16 g_Bh[2048 * 512];
__device__ __nv_bfloat16 g_Bl[2048 * 512];
__device__ __nv_bfloat16 g_Qh[Mm * HD];
__device__ __nv_bfloat16 g_Ql[Mm * HD];
// K/V stored COMPACTED per batch: row = b*512 + compacted_pos
__device__ __nv_bfloat16 g_Kh[Mm * HD];
__device__ __nv_bfloat16 g_Kl[Mm * HD];
__device__ __nv_bfloat16 g_Vh[Mm * HD];
__device__ __nv_bfloat16 g_Vl[Mm * HD];
// mask compaction
__device__ int g_idx[Bb * Ss];
__device__ int g_nt[Bb];
__device__ int g_nk[Bb];

// ---------------------------------------------------------------- helpers
__device__ __forceinline__ void pack_hilo(float v0, float v1, uint32_t& hp, uint32_t& lp) {
    asm("cvt.rn.bf16x2.f32 %0, %1, %2;" : "=r"(hp) : "f"(v1), "f"(v0));
    float h0 = __uint_as_float(hp << 16);
    float h1 = __uint_as_float(hp & 0xFFFF0000u);
    float r0 = v0 - h0;
    float r1 = v1 - h1;
    asm("cvt.rn.bf16x2.f32 %0, %1, %2;" : "=r"(lp) : "f"(r1), "f"(r0));
}
__device__ __forceinline__ float ex2(float x) {
    float r;
    asm("ex2.approx.f32 %0, %1;" : "=f"(r) : "f"(x));
    return r;
}
__device__ __forceinline__ uint32_t smem_u32(const void* p) {
    uint32_t a;
    asm("{ .reg .u64 t; cvta.to.shared.u64 t, %1; cvt.u32.u64 %0, t; }" : "=r"(a) : "l"(p));
    return a;
}
__device__ __forceinline__ void ldsm4(uint32_t r[4], uint32_t addr) {
    asm volatile("ldmatrix.sync.aligned.m8n8.x4.shared.b16 {%0,%1,%2,%3}, [%4];"
                 : "=r"(r[0]), "=r"(r[1]), "=r"(r[2]), "=r"(r[3]) : "r"(addr));
}
__device__ __forceinline__ void ldsm4t(uint32_t r[4], uint32_t addr) {
    asm volatile("ldmatrix.sync.aligned.m8n8.x4.trans.shared.b16 {%0,%1,%2,%3}, [%4];"
                 : "=r"(r[0]), "=r"(r[1]), "=r"(r[2]), "=r"(r[3]) : "r"(addr));
}
__device__ __forceinline__ void mma16816(float d[4], const uint32_t a[4],
                                         uint32_t b0, uint32_t b1) {
    asm volatile("mma.sync.aligned.m16n8k16.row.col.f32.bf16.bf16.f32 "
                 "{%0,%1,%2,%3}, {%4,%5,%6,%7}, {%8,%9}, {%0,%1,%2,%3};"
                 : "+f"(d[0]), "+f"(d[1]), "+f"(d[2]), "+f"(d[3])
                 : "r"(a[0]), "r"(a[1]), "r"(a[2]), "r"(a[3]), "r"(b0), "r"(b1));
}
__device__ __forceinline__ void cpasync16(uint32_t saddr, const void* g) {
    asm volatile("cp.async.cg.shared.global [%0], [%1], 16;" :: "r"(saddr), "l"(g));
}
__device__ __forceinline__ void cpcommit() {
    asm volatile("cp.async.commit_group;" ::: "memory");
}
template <int N>
__device__ __forceinline__ void cpwait() {
    asm volatile("cp.async.wait_group %0;" :: "n"(N) : "memory");
}

// ---------------------------------------------------------------- fused prep
// blocks [0, 16384):      A = x + BE split to hi/lo
// blocks [16384, 20480):  weights W^T split to hi/lo
// blocks [20480, 20544):  mask compaction (one block per batch, 256 threads,
//                         each thread covers key positions t and t+256)
__global__ __launch_bounds__(256) void prep_kernel(const float* __restrict__ x,
                                                   const float* __restrict__ be,
                                                   const float* __restrict__ WQ,
                                                   const float* __restrict__ WK,
                                                   const float* __restrict__ WV,
                                                   const float* __restrict__ WO,
                                                   const float* __restrict__ mask) {
    if (blockIdx.x < 16384) {
        uint32_t i4 = blockIdx.x * 256 + threadIdx.x;
        int m = i4 >> 7;
        int k = (i4 & 127) << 2;
        const float4 xv = *(const float4*)&x[(size_t)m * Ee + k];
        const float4 bv = *(const float4*)&be[(size_t)(m & (Ss - 1)) * Ee + k];
        uint32_t h01, h23, l01, l23;
        pack_hilo(xv.x + bv.x, xv.y + bv.y, h01, l01);
        pack_hilo(xv.z + bv.z, xv.w + bv.w, h23, l23);
        size_t o = (size_t)m * Ee + k;
        *(uint32_t*)&g_Ah[o]     = h01;
        *(uint32_t*)&g_Ah[o + 2] = h23;
        *(uint32_t*)&g_Al[o]     = l01;
        *(uint32_t*)&g_Al[o + 2] = l23;
    } else if (blockIdx.x < 20480) {
        uint32_t idx = (blockIdx.x - 16384) * 256 + threadIdx.x;
        int r = idx >> 9;
        int k = idx & 511;
        float v;
        if (r < 1536) {
            int z = r >> 9;
            int n = r & 511;
            const float* W = (z == 0) ? WQ : (z == 1) ? WK : WV;
            v = W[(size_t)(n >> 6) * (Ee * Dd) + (size_t)k * Dd + (n & 63)];
        } else {
            int n = r - 1536;
            v = WO[(size_t)k * Ee + n];
        }
        uint32_t hp, lp;
        pack_hilo(v, v, hp, lp);
        g_Bh[idx] = *(__nv_bfloat16*)&hp;
        g_Bl[idx] = *(__nv_bfloat16*)&lp;
    } else {
        // ---- mask compaction, batch b, 256 threads x 2 positions
        const int b = blockIdx.x - 20480;
        const int t = threadIdx.x;
        const int w = t >> 5, lane = t & 31;
        const bool keep0 = (mask[(size_t)b * 512 + t] == 0.0f);
        const bool keep1 = (mask[(size_t)b * 512 + t + 256] == 0.0f);
        const unsigned bal0 = __ballot_sync(0xffffffffu, keep0);
        const unsigned bal1 = __ballot_sync(0xffffffffu, keep1);
        __shared__ int wcnt[16], woff[16], snk;
        if (lane == 0) {
            wcnt[w]     = __popc(bal0);   // segment w   covers keys [w*32, w*32+32)
            wcnt[8 + w] = __popc(bal1);   // segment 8+w covers keys [256+w*32, ...)
        }
        __syncthreads();
        if (t == 0) {
            int s = 0;
            for (int i = 0; i < 16; i++) { woff[i] = s; s += wcnt[i]; }
            snk = s;
            g_nk[b] = s;
            g_nt[b] = (s + 63) >> 6;
        }
        __syncthreads();
        const int nk = snk;
        const unsigned lm = (1u << lane) - 1u;
        if (keep0) g_idx[b * 512 + woff[w]     + __popc(bal0 & lm)] = t;
        if (keep1) g_idx[b * 512 + woff[8 + w] + __popc(bal1 & lm)] = t + 256;
        if (t >= nk)       g_idx[b * 512 + t]       = 0;
        if (t + 256 >= nk) g_idx[b * 512 + t + 256] = 0;
    }
}

// ---------------------------------------------------------------- HMMA GEMM
// 128x128 CTA, 4 warps, warp tile 64x64, cp.async 3-stage.
static constexpr int SA_H = 0;
static constexpr int SA_L = 8192;
static constexpr int SB_H = 16384;
static constexpr int SB_L = 24576;
static constexpr int GSTAGE = 32768;
static constexpr int GEMM_SMEM = 3 * GSTAGE;   // 96 KB

static constexpr float SCALE2 = 0.044194173824159216f * 1.4426950408889634f; // 1/sqrt(E)*log2(e)

template <int WHICH>
__global__ __launch_bounds__(128, 2) void gemm_bf16x3_kernel(float* __restrict__ Cout)
{
    extern __shared__ __align__(16) char sm[];
    const uint32_t sb = smem_u32(sm);
    const int tid  = threadIdx.x;
    const int wid  = tid >> 5;
    const int lane = tid & 31;

    const int mt = blockIdx.x;
    const int m0 = mt * 128;
    const int n0 = blockIdx.y * 128;
    const int z  = (WHICH == 0) ? blockIdx.z : 0;

    const int bb = mt >> 2;
    const int lt = mt & 3;
    if (WHICH == 0 && z > 0) {
        const int ntk = (g_nk[bb] + 127) >> 7;
        if (lt >= ntk) return;
    }

    const __nv_bfloat16* Ah = (WHICH == 0) ? g_Ah : g_ATh;
    const __nv_bfloat16* Al = (WHICH == 0) ? g_Al : g_ATl;
    const size_t boff = (WHICH == 0) ? (size_t)z * 512 * 512 : (size_t)1536 * 512;
    const __nv_bfloat16* Bh = g_Bh + boff;
    const __nv_bfloat16* Bl = g_Bl + boff;

    const int m_warp = (wid & 1) * 64;
    const int n_warp = (wid >> 1) * 64;

    const int rA   = (lane & 7) + ((lane >> 3) & 1) * 8;
    const int kbA  = lane >> 4;
    const int sxA  = (rA >> 1) & 3;
    const int rB   = (lane & 7) + (lane >> 4) * 8;
    const int kbB  = (lane >> 3) & 1;
    const int sxB  = (rB >> 1) & 3;

    float acc[4][8][4];
#pragma unroll
    for (int i = 0; i < 4; i++)
#pragma unroll
        for (int j = 0; j < 8; j++)
#pragma unroll
            for (int u = 0; u < 4; u++) acc[i][j][u] = 0.f;

    int grow[4], gc8[4];
    uint32_t so[4];
    size_t aoff[4], bo[4];
#pragma unroll
    for (int i = 0; i < 4; i++) {
        int f = tid + i * 128;
        grow[i] = f >> 2;
        gc8[i]  = f & 3;
        so[i]   = grow[i] * 64 + ((gc8[i] ^ ((grow[i] >> 1) & 3)) * 16);
        int arow = m0 + grow[i];
        if (WHICH == 0 && z > 0)
            arow = bb * 512 + g_idx[bb * 512 + (lt * 128 + grow[i])];
        aoff[i] = (size_t)arow * 512 + gc8[i] * 8;
        bo[i]   = (size_t)(n0 + grow[i]) * 512 + gc8[i] * 8;
    }

    auto load_chunk = [&](int k0, int stage) {
        uint32_t s_ = sb + stage * GSTAGE;
#pragma unroll
        for (int i = 0; i < 4; i++) {
            cpasync16(s_ + SA_H + so[i], Ah + aoff[i] + k0);
            cpasync16(s_ + SA_L + so[i], Al + aoff[i] + k0);
            cpasync16(s_ + SB_H + so[i], Bh + bo[i] + k0);
            cpasync16(s_ + SB_L + so[i], Bl + bo[i] + k0);
        }
        cpcommit();
    };

    load_chunk(0, 0);
    load_chunk(32, 1);

    for (int c = 0; c < 16; ++c) {
        if (c < 15) cpwait<1>(); else cpwait<0>();
        __syncthreads();
        if (c + 2 < 16) load_chunk((c + 2) * 32, (c + 2) % 3);

        const uint32_t sbs = sb + (c % 3) * GSTAGE;
#pragma unroll
        for (int kk = 0; kk < 2; ++kk) {
            uint32_t ah[4][4], al[4][4];
#pragma unroll
            for (int tm = 0; tm < 4; ++tm) {
                uint32_t ro = (uint32_t)(m_warp + tm * 16 + rA) * 64 +
                              (uint32_t)(((kk * 2 + kbA) ^ sxA) * 16);
                ldsm4(ah[tm], sbs + SA_H + ro);
                ldsm4(al[tm], sbs + SA_L + ro);
            }
#pragma unroll
            for (int tp = 0; tp < 4; ++tp) {
                uint32_t bh[4], bl[4];
                uint32_t ro = (uint32_t)(n_warp + tp * 16 + rB) * 64 +
                              (uint32_t)(((kk * 2 + kbB) ^ sxB) * 16);
                ldsm4(bh, sbs + SB_H + ro);
                ldsm4(bl, sbs + SB_L + ro);
#pragma unroll
                for (int tm = 0; tm < 4; ++tm) {
                    mma16816(acc[tm][2 * tp],     ah[tm], bh[0], bh[1]);
                    mma16816(acc[tm][2 * tp],     ah[tm], bl[0], bl[1]);
                    mma16816(acc[tm][2 * tp],     al[tm], bh[0], bh[1]);
                    mma16816(acc[tm][2 * tp + 1], ah[tm], bh[2], bh[3]);
                    mma16816(acc[tm][2 * tp + 1], ah[tm], bl[2], bl[3]);
                    mma16816(acc[tm][2 * tp + 1], al[tm], bh[2], bh[3]);
                }
            }
        }
    }

    // epilogue
    if (WHICH == 0) {
        if (z == 0) {
#pragma unroll
            for (int i = 0; i < 4; i++)
#pragma unroll
                for (int j = 0; j < 8; j++)
#pragma unroll
                    for (int u = 0; u < 4; u++) acc[i][j][u] *= SCALE2;
        }
        __nv_bfloat16* Ch = (z == 0) ? g_Qh : (z == 1) ? g_Kh : g_Vh;
        __nv_bfloat16* Cl = (z == 0) ? g_Ql : (z == 1) ? g_Kl : g_Vl;
#pragma unroll
        for (int tm = 0; tm < 4; ++tm) {
            const int m = m0 + m_warp + tm * 16 + (lane >> 2);
#pragma unroll
            for (int tn = 0; tn < 8; ++tn) {
                const int n = n0 + n_warp + tn * 8 + (lane & 3) * 2;
                size_t o0 = (size_t)m * 512 + n;
                size_t o1 = (size_t)(m + 8) * 512 + n;
                uint32_t hp0, lp0, hp1, lp1;
                pack_hilo(acc[tm][tn][0], acc[tm][tn][1], hp0, lp0);
                pack_hilo(acc[tm][tn][2], acc[tm][tn][3], hp1, lp1);
                *(uint32_t*)&Ch[o0] = hp0;
                *(uint32_t*)&Cl[o0] = lp0;
                *(uint32_t*)&Ch[o1] = hp1;
                *(uint32_t*)&Cl[o1] = lp1;
            }
        }
    } else {
#pragma unroll
        for (int tm = 0; tm < 4; ++tm) {
            const int m = m0 + m_warp + tm * 16 + (lane >> 2);
#pragma unroll
            for (int tn = 0; tn < 8; ++tn) {
                const int n = n0 + n_warp + tn * 8 + (lane & 3) * 2;
                *(float2*)&Cout[(size_t)m * 512 + n] =
                    make_float2(acc[tm][tn][0], acc[tm][tn][1]);
                *(float2*)&Cout[(size_t)(m + 8) * 512 + n] =
                    make_float2(acc[tm][tn][2], acc[tm][tn][3]);
            }
        }
    }
}

// ---------------------------------------------------------------- tensor-core attention
// FA2-style, K/V pre-compacted per batch. Full tiles predicate-free; tail tile
// processes only ceil(rem/16) key chunks (skipped chunks contributed exact
// zeros -> bit-identical results).
static constexpr int A_QH = 0;
static constexpr int A_QL = 16384;
static constexpr int A_K0 = 32768;
static constexpr int A_V0 = 65536;
static constexpr int ATTN_SMEM = 98304;

__global__ __launch_bounds__(256, 2) void attn_mma_kernel()
{
    extern __shared__ char sm[];
    const uint32_t sb = smem_u32(sm);
    const int tid  = threadIdx.x;
    const int wid  = tid >> 5;
    const int lane = tid & 31;

    const int qt = blockIdx.x;
    const int h  = blockIdx.y;
    const int b  = blockIdx.z;
    const int mq = wid * 16;
    const size_t qrow0 = (size_t)b * 512 + qt * 128;

    const int nt = g_nt[b];
    const int nk = g_nk[b];
    const int kgmax = ((nk - (nt - 1) * 64) + 15) >> 4;   // tail chunks: 1..4

#pragma unroll
    for (int i = 0; i < 4; i++) {
        int idx = tid + i * 256;
        int row = idx >> 3, c = idx & 7;
        uint32_t so = row * 128 + ((c ^ (row & 7)) * 16);
        size_t g = (qrow0 + row) * 512 + h * 64 + c * 8;
        cpasync16(sb + A_QH + so, &g_Qh[g]);
        cpasync16(sb + A_QL + so, &g_Ql[g]);
    }
#pragma unroll
    for (int i = 0; i < 2; i++) {
        int idx = tid + i * 256;
        int row = idx >> 3, c = idx & 7;
        uint32_t so = row * 128 + ((c ^ (row & 7)) * 16);
        size_t g = ((size_t)b * 512 + row) * 512 + h * 64 + c * 8;
        cpasync16(sb + A_K0 + so, &g_Kh[g]);
        cpasync16(sb + A_K0 + 8192 + so, &g_Kl[g]);
        cpasync16(sb + A_V0 + so, &g_Vh[g]);
        cpasync16(sb + A_V0 + 8192 + so, &g_Vl[g]);
    }
    cpcommit();

    float accO[4][2][4];
#pragma unroll
    for (int i = 0; i < 4; i++)
#pragma unroll
        for (int j = 0; j < 2; j++)
#pragma unroll
            for (int u = 0; u < 4; u++) accO[i][j][u] = 0.f;
    float rs0 = 0.f, rs1 = 0.f;

    const int rowQ = mq + (lane & 7) + ((lane >> 3) & 1) * 8;
    const int cQ   = lane >> 4;
    const int rowK = (lane & 7) + (lane >> 4) * 8;
    const int cK   = (lane >> 3) & 1;
    const int rowV = (lane & 7) + ((lane >> 3) & 1) * 8;
    const int cV   = lane >> 4;

    // ---------------- full tiles (all keys valid: no predicates)
    for (int tile = 0; tile + 1 < nt; ++tile) {
        cpwait<0>();
        __syncthreads();

        {
            const int t1 = (tile + 1) * 64;
            const uint32_t kb1 = sb + A_K0 + ((tile + 1) & 1) * 16384;
            const uint32_t vb1 = sb + A_V0 + ((tile + 1) & 1) * 16384;
#pragma unroll
            for (int i = 0; i < 2; i++) {
                int idx = tid + i * 256;
                int row = idx >> 3, c = idx & 7;
                uint32_t so = row * 128 + ((c ^ (row & 7)) * 16);
                size_t g = ((size_t)b * 512 + t1 + row) * 512 + h * 64 + c * 8;
                cpasync16(kb1 + so, &g_Kh[g]);
                cpasync16(kb1 + 8192 + so, &g_Kl[g]);
                cpasync16(vb1 + so, &g_Vh[g]);
                cpasync16(vb1 + 8192 + so, &g_Vl[g]);
            }
            cpcommit();
        }

        const uint32_t kb = sb + A_K0 + (tile & 1) * 16384;
        const uint32_t vb = sb + A_V0 + (tile & 1) * 16384;

        float accS[4][2][4];
#pragma unroll
        for (int i = 0; i < 4; i++)
#pragma unroll
            for (int j = 0; j < 2; j++)
#pragma unroll
                for (int u = 0; u < 4; u++) accS[i][j][u] = 0.f;

#pragma unroll
        for (int ks = 0; ks < 4; ++ks) {
            uint32_t qh[4], ql[4];
            {
                uint32_t so = rowQ * 128 + (((ks * 2 + cQ) ^ (rowQ & 7)) * 16);
                ldsm4(qh, sb + A_QH + so);
                ldsm4(ql, sb + A_QL + so);
            }
#pragma unroll
            for (int kg = 0; kg < 4; ++kg) {
                uint32_t kh[4], kl[4];
                int row = kg * 16 + rowK;
                uint32_t so = row * 128 + (((ks * 2 + cK) ^ (row & 7)) * 16);
                ldsm4(kh, kb + so);
                ldsm4(kl, kb + 8192 + so);
                mma16816(accS[kg][0], qh, kh[0], kh[1]);
                mma16816(accS[kg][1], qh, kh[2], kh[3]);
                mma16816(accS[kg][0], qh, kl[0], kl[1]);
                mma16816(accS[kg][1], qh, kl[2], kl[3]);
                mma16816(accS[kg][0], ql, kh[0], kh[1]);
                mma16816(accS[kg][1], ql, kh[2], kh[3]);
            }
        }

#pragma unroll
        for (int kc = 0; kc < 4; ++kc) {
            float p[2][4];
#pragma unroll
            for (int t8 = 0; t8 < 2; ++t8) {
                p[t8][0] = ex2(accS[kc][t8][0]);   // scale pre-folded into Q
                p[t8][1] = ex2(accS[kc][t8][1]);
                p[t8][2] = ex2(accS[kc][t8][2]);
                p[t8][3] = ex2(accS[kc][t8][3]);
                rs0 += p[t8][0] + p[t8][1];
                rs1 += p[t8][2] + p[t8][3];
            }
            uint32_t ph[4], pl[4];
            pack_hilo(p[0][0], p[0][1], ph[0], pl[0]);
            pack_hilo(p[0][2], p[0][3], ph[1], pl[1]);
            pack_hilo(p[1][0], p[1][1], ph[2], pl[2]);
            pack_hilo(p[1][2], p[1][3], ph[3], pl[3]);
#pragma unroll
            for (int dg = 0; dg < 4; ++dg) {
                uint32_t vh[4], vl[4];
                int row = kc * 16 + rowV;
                uint32_t so = row * 128 + (((dg * 2 + cV) ^ (row & 7)) * 16);
                ldsm4t(vh, vb + so);
                ldsm4t(vl, vb + 8192 + so);
                mma16816(accO[dg][0], ph, vh[0], vh[1]);
                mma16816(accO[dg][1], ph, vh[2], vh[3]);
                mma16816(accO[dg][0], ph, vl[0], vl[1]);
                mma16816(accO[dg][1], ph, vl[2], vl[3]);
                mma16816(accO[dg][0], pl, vh[0], vh[1]);
                mma16816(accO[dg][1], pl, vh[2], vh[3]);
            }
        }
    }

    // ---------------- tail tile (only kgmax chunks; predicated exp)
    {
        const int tile = nt - 1;
        cpwait<0>();
        __syncthreads();

        const uint32_t kb = sb + A_K0 + (tile & 1) * 16384;
        const uint32_t vb = sb + A_V0 + (tile & 1) * 16384;

        float accS[4][2][4];
#pragma unroll
        for (int i = 0; i < 4; i++)
#pragma unroll
            for (int j = 0; j < 2; j++)
#pragma unroll
                for (int u = 0; u < 4; u++) accS[i][j][u] = 0.f;

#pragma unroll
        for (int ks = 0; ks < 4; ++ks) {
            uint32_t qh[4], ql[4];
            {
                uint32_t so = rowQ * 128 + (((ks * 2 + cQ) ^ (rowQ & 7)) * 16);
                ldsm4(qh, sb + A_QH + so);
                ldsm4(ql, sb + A_QL + so);
            }
#pragma unroll
            for (int kg = 0; kg < 4; ++kg) {
                if (kg < kgmax) {
                    uint32_t kh[4], kl[4];
                    int row = kg * 16 + rowK;
                    uint32_t so = row * 128 + (((ks * 2 + cK) ^ (row & 7)) * 16);
                    ldsm4(kh, kb + so);
                    ldsm4(kl, kb + 8192 + so);
                    mma16816(accS[kg][0], qh, kh[0], kh[1]);
                    mma16816(accS[kg][1], qh, kh[2], kh[3]);
                    mma16816(accS[kg][0], qh, kl[0], kl[1]);
                    mma16816(accS[kg][1], qh, kl[2], kl[3]);
                    mma16816(accS[kg][0], ql, kh[0], kh[1]);
                    mma16816(accS[kg][1], ql, kh[2], kh[3]);
                }
            }
        }

        const int t0 = tile * 64;
#pragma unroll
        for (int kc = 0; kc < 4; ++kc) {
            if (kc < kgmax) {
                float p[2][4];
#pragma unroll
                for (int t8 = 0; t8 < 2; ++t8) {
                    int key = t0 + kc * 16 + t8 * 8 + (lane & 3) * 2;
                    bool v0 = key < nk;
                    bool v1 = key + 1 < nk;
                    p[t8][0] = v0 ? ex2(accS[kc][t8][0]) : 0.f;
                    p[t8][1] = v1 ? ex2(accS[kc][t8][1]) : 0.f;
                    p[t8][2] = v0 ? ex2(accS[kc][t8][2]) : 0.f;
                    p[t8][3] = v1 ? ex2(accS[kc][t8][3]) : 0.f;
                    rs0 += p[t8][0] + p[t8][1];
                    rs1 += p[t8][2] + p[t8][3];
                }
                uint32_t ph[4], pl[4];
                pack_hilo(p[0][0], p[0][1], ph[0], pl[0]);
                pack_hilo(p[0][2], p[0][3], ph[1], pl[1]);
                pack_hilo(p[1][0], p[1][1], ph[2], pl[2]);
                pack_hilo(p[1][2], p[1][3], ph[3], pl[3]);
#pragma unroll
                for (int dg = 0; dg < 4; ++dg) {
                    uint32_t vh[4], vl[4];
                    int row = kc * 16 + rowV;
                    uint32_t so = row * 128 + (((dg * 2 + cV) ^ (row & 7)) * 16);
                    ldsm4t(vh, vb + so);
                    ldsm4t(vl, vb + 8192 + so);
                    mma16816(accO[dg][0], ph, vh[0], vh[1]);
                    mma16816(accO[dg][1], ph, vh[2], vh[3]);
                    mma16816(accO[dg][0], ph, vl[0], vl[1]);
                    mma16816(accO[dg][1], ph, vl[2], vl[3]);
                    mma16816(accO[dg][0], pl, vh[0], vh[1]);
                    mma16816(accO[dg][1], pl, vh[2], vh[3]);
                }
            }
        }
    }

    rs0 += __shfl_xor_sync(0xffffffffu, rs0, 1);
    rs0 += __shfl_xor_sync(0xffffffffu, rs0, 2);
    rs1 += __shfl_xor_sync(0xffffffffu, rs1, 1);
    rs1 += __shfl_xor_sync(0xffffffffu, rs1, 2);
    const float inv0 = 1.f / rs0;
    const float inv1 = 1.f / rs1;

    const int r0 = mq + (lane >> 2);
    const int r1 = r0 + 8;
    const size_t g0 = (qrow0 + r0) * 512 + h * 64;
    const size_t g1 = (qrow0 + r1) * 512 + h * 64;
#pragma unroll
    for (int dg = 0; dg < 4; ++dg) {
#pragma unroll
        for (int t8 = 0; t8 < 2; ++t8) {
            int d = dg * 16 + t8 * 8 + (lane & 3) * 2;
            uint32_t hp0, lp0, hp1, lp1;
            pack_hilo(accO[dg][t8][0] * inv0, accO[dg][t8][1] * inv0, hp0, lp0);
            pack_hilo(accO[dg][t8][2] * inv1, accO[dg][t8][3] * inv1, hp1, lp1);
            *(uint32_t*)&g_ATh[g0 + d] = hp0;
            *(uint32_t*)&g_ATl[g0 + d] = lp0;
            *(uint32_t*)&g_ATh[g1 + d] = hp1;
            *(uint32_t*)&g_ATl[g1 + d] = lp1;
        }
    }
}

// ---------------------------------------------------------------- launch
extern "C" void kernel_launch(void* const* d_in, const int* in_sizes, int n_in,
                              void* d_out, int out_size)
{
    const float* x    = (const float*)d_in[0];
    const float* mask = (const float*)d_in[1];
    const float* WQ   = (const float*)d_in[2];
    const float* WK   = (const float*)d_in[3];
    const float* WV   = (const float*)d_in[4];
    const float* BE   = (const float*)d_in[5];
    const float* WO   = (const float*)d_in[6];
    float* out        = (float*)d_out;

    cudaFuncSetAttribute(attn_mma_kernel,
                         cudaFuncAttributeMaxDynamicSharedMemorySize, ATTN_SMEM);
    cudaFuncSetAttribute(gemm_bf16x3_kernel<0>,
                         cudaFuncAttributeMaxDynamicSharedMemorySize, GEMM_SMEM);
    cudaFuncSetAttribute(gemm_bf16x3_kernel<1>,
                         cudaFuncAttributeMaxDynamicSharedMemorySize, GEMM_SMEM);

    prep_kernel<<<16384 + 4096 + 64, 256>>>(x, BE, WQ, WK, WV, WO, mask);

    dim3 gq(Mm / 128, 512 / 128, 3);
    gemm_bf16x3_kernel<0><<<gq, 128, GEMM_SMEM>>>(nullptr);

    dim3 ga(Ss / 128, Hh, Bb);
    attn_mma_kernel<<<ga, 256, ATTN_SMEM>>>();

    dim3 go(Mm / 128, 512 / 128);
    gemm_bf16x3_kernel<1><<<go, 128, GEMM_SMEM>>>(out);
}